// round 1
// baseline (speedup 1.0000x reference)
#include <cuda_runtime.h>
#include <math.h>

#define NPTS 4096
#define LCH  512
#define ICH  1024
#define HWD  256
#define HEADS 4

// ---------------- scratch (device globals; no allocations allowed) ----------
struct PP { int x0, x1, y0, y1; float wa, wb, wc, wd; };
__device__ PP    g_pp[NPTS];
__device__ float g_img [ICH * NPTS];          // img_features  [c][n]   16 MB
__device__ float g_Lq  [LCH * NPTS];          // L_query       [l][n]    8 MB
__device__ float g_keys[HEADS * LCH * NPTS];  // keys          [h][l][n] 32 MB
__device__ float g_t   [LCH * NPTS];          // t (pre/post LN)         8 MB
__device__ float g_wmap[HEADS * NPTS];        // weightmap     [h][n]

// ---------------- 1) per-point bilinear params ------------------------------
__global__ void prep_points(const float* __restrict__ kp) {
    int n = blockIdx.x * blockDim.x + threadIdx.x;
    if (n >= NPTS) return;
    float x = kp[n * 4 + 1] * 256.0f;   // (kp - 0) / (1/256) / 1
    float y = kp[n * 4 + 2] * 256.0f;
    int fx = (int)floorf(x);
    int fy = (int)floorf(y);
    int x0 = min(max(fx,     0), HWD - 1);
    int x1 = min(max(fx + 1, 0), HWD - 1);
    int y0 = min(max(fy,     0), HWD - 1);
    int y1 = min(max(fy + 1, 0), HWD - 1);
    float x0f = (float)x0, x1f = (float)x1, y0f = (float)y0, y1f = (float)y1;
    PP p;
    p.x0 = x0; p.x1 = x1; p.y0 = y0; p.y1 = y1;
    p.wa = (x1f - x) * (y1f - y);
    p.wb = (x1f - x) * (y - y0f);
    p.wc = (x - x0f) * (y1f - y);
    p.wd = (x - x0f) * (y - y0f);
    g_pp[n] = p;
}

// ---------------- 2) BEV gather -> g_img[c][n] ------------------------------
__global__ void gather_bev(const float* __restrict__ bev) {
    int n = blockIdx.x * blockDim.x + threadIdx.x;  // 0..4095
    int c = blockIdx.y;                              // 0..1023
    PP p = g_pp[n];
    const float* pl = bev + (size_t)c * (HWD * HWD);
    float v = p.wa * pl[p.y0 * HWD + p.x0]
            + p.wb * pl[p.y1 * HWD + p.x0]
            + p.wc * pl[p.y0 * HWD + p.x1]
            + p.wd * pl[p.y1 * HWD + p.x1];
    g_img[(size_t)c * NPTS + n] = v;
}

// ---------------- 3) SGEMM:  C[MxN] = A[MxK] @ B[KxN] + bias[m] -------------
// BM=BN=128, BK=8, TM=TN=8, 256 threads. M,N,K all multiples of tile sizes.
__global__ __launch_bounds__(256)
void sgemm_bias(const float* __restrict__ A, const float* __restrict__ B,
                const float* __restrict__ bias, float* __restrict__ C,
                int M, int N, int K) {
    const int BM = 128, BN = 128, BK = 8, TM = 8, TN = 8;
    __shared__ float As[BK][BM];
    __shared__ float Bs[BK][BN];

    int tid = threadIdx.x;
    int bm = blockIdx.y * BM;
    int bn = blockIdx.x * BN;

    int tr = (tid / (BN / TN)) * TM;   // 0,8,...,120
    int tc = (tid % (BN / TN)) * TN;

    // A loader: 128 rows x 8 cols; thread -> row tid/2, col (tid%2)*4, float4
    int aRow = tid >> 1;
    int aCol = (tid & 1) * 4;
    // B loader: 8 rows x 128 cols; thread -> row tid/32, col (tid%32)*4
    int bRow = tid >> 5;
    int bCol = (tid & 31) * 4;

    float acc[TM][TN];
    #pragma unroll
    for (int i = 0; i < TM; i++)
        #pragma unroll
        for (int j = 0; j < TN; j++) acc[i][j] = 0.0f;

    for (int k0 = 0; k0 < K; k0 += BK) {
        float4 av = *(const float4*)(A + (size_t)(bm + aRow) * K + k0 + aCol);
        As[aCol + 0][aRow] = av.x;
        As[aCol + 1][aRow] = av.y;
        As[aCol + 2][aRow] = av.z;
        As[aCol + 3][aRow] = av.w;
        *(float4*)&Bs[bRow][bCol] =
            *(const float4*)(B + (size_t)(k0 + bRow) * N + bn + bCol);
        __syncthreads();

        #pragma unroll
        for (int k = 0; k < BK; k++) {
            float4 a0 = *(float4*)&As[k][tr];
            float4 a1 = *(float4*)&As[k][tr + 4];
            float4 b0 = *(float4*)&Bs[k][tc];
            float4 b1 = *(float4*)&Bs[k][tc + 4];
            float a[TM] = {a0.x, a0.y, a0.z, a0.w, a1.x, a1.y, a1.z, a1.w};
            float b[TN] = {b0.x, b0.y, b0.z, b0.w, b1.x, b1.y, b1.z, b1.w};
            #pragma unroll
            for (int i = 0; i < TM; i++)
                #pragma unroll
                for (int j = 0; j < TN; j++)
                    acc[i][j] += a[i] * b[j];
        }
        __syncthreads();
    }

    #pragma unroll
    for (int i = 0; i < TM; i++) {
        float bi = bias ? bias[bm + tr + i] : 0.0f;
        #pragma unroll
        for (int j = 0; j < TN; j += 4) {
            float4 v;
            v.x = acc[i][j + 0] + bi;
            v.y = acc[i][j + 1] + bi;
            v.z = acc[i][j + 2] + bi;
            v.w = acc[i][j + 3] + bi;
            *(float4*)(C + (size_t)(bm + tr + i) * N + bn + tc + j) = v;
        }
    }
}

// ---------------- 4) score + softmax over heads -> g_wmap -------------------
__global__ void score_softmax() {
    int n = blockIdx.x * blockDim.x + threadIdx.x;  // 0..4095
    float a0 = 0.f, a1 = 0.f, a2 = 0.f, a3 = 0.f;
    for (int l = 0; l < LCH; l++) {
        float lq = g_Lq[l * NPTS + n];
        a0 += g_keys[(0 * LCH + l) * NPTS + n] * lq;
        a1 += g_keys[(1 * LCH + l) * NPTS + n] * lq;
        a2 += g_keys[(2 * LCH + l) * NPTS + n] * lq;
        a3 += g_keys[(3 * LCH + l) * NPTS + n] * lq;
    }
    const float inv = 0.04419417382415922f;  // 1/sqrt(512)
    a0 *= inv; a1 *= inv; a2 *= inv; a3 *= inv;
    float m = fmaxf(fmaxf(a0, a1), fmaxf(a2, a3));
    float e0 = expf(a0 - m), e1 = expf(a1 - m), e2 = expf(a2 - m), e3 = expf(a3 - m);
    float s = e0 + e1 + e2 + e3;
    g_wmap[0 * NPTS + n] = e0 / s;
    g_wmap[1 * NPTS + n] = e1 / s;
    g_wmap[2 * NPTS + n] = e2 / s;
    g_wmap[3 * NPTS + n] = e3 / s;
}

// ---------------- 5) t = z + L_query ---------------------------------------
__global__ void compute_t() {
    size_t i = (size_t)blockIdx.x * blockDim.x + threadIdx.x;  // over LCH*NPTS
    int n = (int)(i & (NPTS - 1));
    float w0 = g_wmap[0 * NPTS + n];
    float w1 = g_wmap[1 * NPTS + n];
    float w2 = g_wmap[2 * NPTS + n];
    float w3 = g_wmap[3 * NPTS + n];
    const size_t HS = (size_t)LCH * NPTS;
    float z = w0 * g_keys[i] + w1 * g_keys[HS + i]
            + w2 * g_keys[2 * HS + i] + w3 * g_keys[3 * HS + i];
    g_t[i] = z + g_Lq[i];
}

// ---------------- 6) LayerNorm over the 4096 point axis (per channel) -------
__global__ __launch_bounds__(256)
void layernorm(const float* __restrict__ lnw, const float* __restrict__ lnb) {
    int l = blockIdx.x;
    float* row = g_t + (size_t)l * NPTS;
    float s = 0.f, ss = 0.f;
    for (int n = threadIdx.x; n < NPTS; n += 256) {
        float v = row[n];
        s += v; ss += v * v;
    }
    // block reduce
    __shared__ float rs[8], rss[8];
    for (int o = 16; o > 0; o >>= 1) {
        s  += __shfl_down_sync(0xffffffffu, s,  o);
        ss += __shfl_down_sync(0xffffffffu, ss, o);
    }
    int wid = threadIdx.x >> 5, lid = threadIdx.x & 31;
    if (lid == 0) { rs[wid] = s; rss[wid] = ss; }
    __syncthreads();
    if (wid == 0) {
        s  = (lid < 8) ? rs[lid]  : 0.f;
        ss = (lid < 8) ? rss[lid] : 0.f;
        for (int o = 4; o > 0; o >>= 1) {
            s  += __shfl_down_sync(0xffffffffu, s,  o);
            ss += __shfl_down_sync(0xffffffffu, ss, o);
        }
        if (lid == 0) { rs[0] = s; rss[0] = ss; }
    }
    __syncthreads();
    float mu = rs[0] * (1.0f / NPTS);
    float var = rss[0] * (1.0f / NPTS) - mu * mu;
    float rstd = rsqrtf(var + 1e-5f);
    for (int n = threadIdx.x; n < NPTS; n += 256)
        row[n] = (row[n] - mu) * rstd * lnw[n] + lnb[n];
}

// ---------------- 7) weightmap copy to output tail --------------------------
__global__ void copy_wmap(float* __restrict__ out) {
    int i = blockIdx.x * blockDim.x + threadIdx.x;
    if (i < HEADS * NPTS) out[i] = g_wmap[i];
}

// ---------------- launch ----------------------------------------------------
extern "C" void kernel_launch(void* const* d_in, const int* in_sizes, int n_in,
                              void* d_out, int out_size) {
    const float* point_features = (const float*)d_in[0];  // (1,512,4096)
    const float* keypoints      = (const float*)d_in[1];  // (4096,4)
    const float* bev_features   = (const float*)d_in[2];  // (1,1024,256,256)
    const float* conv_L_w       = (const float*)d_in[3];  // (512,512)
    const float* conv_L_b       = (const float*)d_in[4];  // (512,)
    const float* img_head_w     = (const float*)d_in[5];  // (4,512,1024)
    const float* img_head_b     = (const float*)d_in[6];  // (4,512)
    const float* ln_w           = (const float*)d_in[7];  // (4096,)
    const float* ln_b           = (const float*)d_in[8];  // (4096,)
    const float* conv_fusion_w  = (const float*)d_in[9];  // (512,512)
    const float* conv_fusion_b  = (const float*)d_in[10]; // (512,)
    float* out = (float*)d_out;

    // device-global scratch addresses are linked directly into the kernels.

    // 1) bilinear params
    prep_points<<<(NPTS + 255) / 256, 256>>>(keypoints);

    // 2) gather BEV -> g_img (1024 x 4096)
    gather_bev<<<dim3(NPTS / 256, ICH), 256>>>(bev_features);

    // 3) L_query = conv_L_w @ point_features + b   (512 x 4096, K=512)
    {
        float* Lq;  cudaGetSymbolAddress((void**)&Lq, g_Lq);
        sgemm_bias<<<dim3(NPTS / 128, LCH / 128), 256>>>(
            conv_L_w, point_features, conv_L_b, Lq, LCH, NPTS, LCH);
    }

    // 4) keys = img_head_w @ g_img + b   (2048 x 4096, K=1024)
    {
        float* img;  cudaGetSymbolAddress((void**)&img, g_img);
        float* keys; cudaGetSymbolAddress((void**)&keys, g_keys);
        sgemm_bias<<<dim3(NPTS / 128, (HEADS * LCH) / 128), 256>>>(
            img_head_w, img, img_head_b, keys, HEADS * LCH, NPTS, ICH);
    }

    // 5) score + softmax
    score_softmax<<<NPTS / 256, 256>>>();

    // 6) t = z + L_query
    compute_t<<<(LCH * NPTS) / 256, 256>>>();

    // 7) LayerNorm over point axis
    layernorm<<<LCH, 256>>>(ln_w, ln_b);

    // 8) fusion = conv_fusion_w @ t + b  ->  out[0 .. 512*4096)
    {
        float* t; cudaGetSymbolAddress((void**)&t, g_t);
        sgemm_bias<<<dim3(NPTS / 128, LCH / 128), 256>>>(
            conv_fusion_w, t, conv_fusion_b, out, LCH, NPTS, LCH);
    }

    // 9) weightmap tail, if the output buffer includes it
    if (out_size >= LCH * NPTS + HEADS * NPTS) {
        copy_wmap<<<(HEADS * NPTS + 255) / 256, 256>>>(out + (size_t)LCH * NPTS);
    }
}

// round 5
// speedup vs baseline: 1.8296x; 1.8296x over previous
#include <cuda_runtime.h>
#include <cuda_bf16.h>
#include <math.h>
#include <cstdint>

#define NPTS 4096
#define LCH  512
#define ICH  1024
#define HWD  256
#define HEADS 4

// ========================= helpers =========================================
__device__ __forceinline__ uint32_t smem_to_u32(const void* smem_ptr) {
    uint32_t addr;
    asm("{ .reg .u64 tmp; cvta.to.shared.u64 tmp, %1; cvt.u32.u64 %0, tmp; }"
        : "=r"(addr) : "l"(smem_ptr));
    return addr;
}
__device__ __forceinline__ void cp_async16(uint32_t dst_smem, const void* src) {
    asm volatile("cp.async.cg.shared.global [%0], [%1], 16;"
        :: "r"(dst_smem), "l"((unsigned long long)__cvta_generic_to_global(src)) : "memory");
}
#define CP_ASYNC_COMMIT() asm volatile("cp.async.commit_group;" ::: "memory")
#define CP_ASYNC_WAIT(n)  asm volatile("cp.async.wait_group %0;" :: "n"(n) : "memory")

__device__ __forceinline__ void ldsm_x4(uint32_t (&r)[4], uint32_t addr) {
    asm volatile("ldmatrix.sync.aligned.m8n8.x4.shared.b16 {%0,%1,%2,%3}, [%4];"
        : "=r"(r[0]), "=r"(r[1]), "=r"(r[2]), "=r"(r[3]) : "r"(addr));
}
__device__ __forceinline__ void ldsm_x2(uint32_t (&r)[2], uint32_t addr) {
    asm volatile("ldmatrix.sync.aligned.m8n8.x2.shared.b16 {%0,%1}, [%2];"
        : "=r"(r[0]), "=r"(r[1]) : "r"(addr));
}
__device__ __forceinline__ void mma_bf16(float (&d)[4], const uint32_t (&a)[4],
                                         const uint32_t (&b)[2]) {
    asm volatile(
        "mma.sync.aligned.m16n8k16.row.col.f32.bf16.bf16.f32 "
        "{%0,%1,%2,%3}, {%4,%5,%6,%7}, {%8,%9}, {%0,%1,%2,%3};"
        : "+f"(d[0]), "+f"(d[1]), "+f"(d[2]), "+f"(d[3])
        : "r"(a[0]), "r"(a[1]), "r"(a[2]), "r"(a[3]), "r"(b[0]), "r"(b[1]));
}

// ========================= scratch globals =================================
struct PP { int x0, x1, y0, y1; float wa, wb, wc, wd; };
__device__ PP    g_pp[NPTS];
__device__ float g_img [ICH * NPTS];
__device__ float g_Lq  [LCH * NPTS];
__device__ float g_keys[HEADS * LCH * NPTS];
__device__ float g_t   [LCH * NPTS];
__device__ float g_wmap[HEADS * NPTS];

// bf16 split operands (A: [M][K] K-major; BT: [N][K] K-major)
__device__ __nv_bfloat16 g_wK_hi[HEADS * LCH * ICH], g_wK_lo[HEADS * LCH * ICH];
__device__ __nv_bfloat16 g_wL_hi[LCH * LCH],         g_wL_lo[LCH * LCH];
__device__ __nv_bfloat16 g_wF_hi[LCH * LCH],         g_wF_lo[LCH * LCH];
__device__ __nv_bfloat16 g_imgT_hi[NPTS * ICH],      g_imgT_lo[NPTS * ICH];
__device__ __nv_bfloat16 g_pfT_hi [NPTS * LCH],      g_pfT_lo [NPTS * LCH];
__device__ __nv_bfloat16 g_tT_hi  [NPTS * LCH],      g_tT_lo  [NPTS * LCH];

// ========================= small kernels ===================================
__global__ void prep_points(const float* __restrict__ kp) {
    int n = blockIdx.x * blockDim.x + threadIdx.x;
    if (n >= NPTS) return;
    float x = kp[n * 4 + 1] * 256.0f;
    float y = kp[n * 4 + 2] * 256.0f;
    int fx = (int)floorf(x);
    int fy = (int)floorf(y);
    int x0 = min(max(fx,     0), HWD - 1);
    int x1 = min(max(fx + 1, 0), HWD - 1);
    int y0 = min(max(fy,     0), HWD - 1);
    int y1 = min(max(fy + 1, 0), HWD - 1);
    float x0f = (float)x0, x1f = (float)x1, y0f = (float)y0, y1f = (float)y1;
    PP p;
    p.x0 = x0; p.x1 = x1; p.y0 = y0; p.y1 = y1;
    p.wa = (x1f - x) * (y1f - y);
    p.wb = (x1f - x) * (y - y0f);
    p.wc = (x - x0f) * (y1f - y);
    p.wd = (x - x0f) * (y - y0f);
    g_pp[n] = p;
}

__global__ void gather_bev(const float* __restrict__ bev) {
    int n = blockIdx.x * blockDim.x + threadIdx.x;
    int c = blockIdx.y;
    PP p = g_pp[n];
    const float* pl = bev + (size_t)c * (HWD * HWD);
    float v = p.wa * pl[p.y0 * HWD + p.x0]
            + p.wb * pl[p.y1 * HWD + p.x0]
            + p.wc * pl[p.y0 * HWD + p.x1]
            + p.wd * pl[p.y1 * HWD + p.x1];
    g_img[(size_t)c * NPTS + n] = v;
}

__global__ void cvt_split(const float* __restrict__ src,
                          __nv_bfloat16* __restrict__ hi,
                          __nv_bfloat16* __restrict__ lo, int count) {
    int i = blockIdx.x * blockDim.x + threadIdx.x;
    if (i >= count) return;
    float v = src[i];
    __nv_bfloat16 h = __float2bfloat16(v);
    hi[i] = h;
    lo[i] = __float2bfloat16(v - __bfloat162float(h));
}

// fp32 [K][N] -> bf16 hi/lo [N][K] (transpose + split), 32x32 tiles
__global__ __launch_bounds__(256)
void cvt_split_T(const float* __restrict__ src,
                 __nv_bfloat16* __restrict__ hiT,
                 __nv_bfloat16* __restrict__ loT, int K, int N) {
    __shared__ float tile[32][33];
    int n0 = blockIdx.x * 32;
    int k0 = blockIdx.y * 32;
    int tx = threadIdx.x & 31;
    int ty = threadIdx.x >> 5;
    #pragma unroll
    for (int j = 0; j < 4; j++) {
        int k = k0 + ty + j * 8;
        tile[ty + j * 8][tx] = src[(size_t)k * N + n0 + tx];
    }
    __syncthreads();
    #pragma unroll
    for (int j = 0; j < 4; j++) {
        int n = n0 + ty + j * 8;
        float v = tile[tx][ty + j * 8];
        __nv_bfloat16 h = __float2bfloat16(v);
        hiT[(size_t)n * K + k0 + tx] = h;
        loT[(size_t)n * K + k0 + tx] = __float2bfloat16(v - __bfloat162float(h));
    }
}

// ========================= mma.sync split-bf16 GEMM ========================
// C[M][N] = (Ahi+Alo)[M][K] x ((Bhi+Blo)[N][K])^T + bias[m]  (drop lo*lo)
// CTA tile 128x128, K-chunk 32. 8 warps (2x4), warp tile 64x32.
#define RSB   80                      // smem row stride bytes (32 bf16 + pad)
#define TILEB (128 * RSB)             // 10240 bytes per operand tile
#define STAGEB (4 * TILEB)            // Ahi Alo Bhi Blo
#define GEMM_SMEM (2 * STAGEB)        // double buffered = 81920

__global__ __launch_bounds__(256, 2)
void gemm_bf16x3(const __nv_bfloat16* __restrict__ Ahi,
                 const __nv_bfloat16* __restrict__ Alo,
                 const __nv_bfloat16* __restrict__ Bhi,
                 const __nv_bfloat16* __restrict__ Blo,
                 const float* __restrict__ bias,
                 float* __restrict__ C, int M, int N, int K) {
    extern __shared__ char smem[];
    uint32_t sb = smem_to_u32(smem);

    int tid = threadIdx.x;
    int lane = tid & 31, wid = tid >> 5;
    int warp_m = wid & 1;          // 0..1  -> 64-row slab
    int warp_n = wid >> 1;         // 0..3  -> 32-col slab
    int bm = blockIdx.y * 128;
    int bn = blockIdx.x * 128;

    // ldmatrix source offsets (bytes within one operand tile)
    uint32_t aOff[4], bOff[4];
    #pragma unroll
    for (int mi = 0; mi < 4; mi++) {
        int row = warp_m * 64 + mi * 16 + (lane & 15);
        aOff[mi] = (uint32_t)(row * RSB + (lane >> 4) * 16);
    }
    #pragma unroll
    for (int ni = 0; ni < 4; ni++) {
        int row = warp_n * 32 + ni * 8 + (lane & 7);
        bOff[ni] = (uint32_t)(row * RSB + ((lane >> 3) & 1) * 16);
    }

    float acc[4][4][4];
    #pragma unroll
    for (int mi = 0; mi < 4; mi++)
        #pragma unroll
        for (int ni = 0; ni < 4; ni++)
            #pragma unroll
            for (int j = 0; j < 4; j++) acc[mi][ni][j] = 0.0f;

    // cp.async mapping: per tile 512 x 16B; 256 threads x 2 iters
    int ldRow0 = tid >> 2;            // +64 on second iter
    int ldSeg  = tid & 3;             // 16B segment within 64B row

    int nchunks = K >> 5;

    auto load_stage = [&](int stage, int k0) {
        uint32_t s = sb + stage * STAGEB;
        #pragma unroll
        for (int it = 0; it < 2; it++) {
            int row = ldRow0 + it * 64;
            uint32_t so = (uint32_t)(row * RSB + ldSeg * 16);
            size_t goA = (size_t)(bm + row) * K + k0 + ldSeg * 8;
            size_t goB = (size_t)(bn + row) * K + k0 + ldSeg * 8;
            cp_async16(s + 0 * TILEB + so, Ahi + goA);
            cp_async16(s + 1 * TILEB + so, Alo + goA);
            cp_async16(s + 2 * TILEB + so, Bhi + goB);
            cp_async16(s + 3 * TILEB + so, Blo + goB);
        }
    };

    load_stage(0, 0);
    CP_ASYNC_COMMIT();

    for (int c = 0; c < nchunks; c++) {
        if (c + 1 < nchunks) {
            load_stage((c + 1) & 1, (c + 1) << 5);
            CP_ASYNC_COMMIT();
            CP_ASYNC_WAIT(1);
        } else {
            CP_ASYNC_WAIT(0);
        }
        __syncthreads();

        uint32_t s = sb + (c & 1) * STAGEB;
        uint32_t sAh = s, sAl = s + TILEB, sBh = s + 2 * TILEB, sBl = s + 3 * TILEB;

        #pragma unroll
        for (int ks = 0; ks < 2; ks++) {
            uint32_t ko = ks * 32;   // 16 bf16 = 32 bytes
            uint32_t a[4][4], bh[4][2], bl[4][2];
            #pragma unroll
            for (int mi = 0; mi < 4; mi++) ldsm_x4(a[mi], sAh + aOff[mi] + ko);
            #pragma unroll
            for (int ni = 0; ni < 4; ni++) ldsm_x2(bh[ni], sBh + bOff[ni] + ko);
            #pragma unroll
            for (int ni = 0; ni < 4; ni++) ldsm_x2(bl[ni], sBl + bOff[ni] + ko);
            #pragma unroll
            for (int mi = 0; mi < 4; mi++)
                #pragma unroll
                for (int ni = 0; ni < 4; ni++) mma_bf16(acc[mi][ni], a[mi], bh[ni]);
            #pragma unroll
            for (int mi = 0; mi < 4; mi++)
                #pragma unroll
                for (int ni = 0; ni < 4; ni++) mma_bf16(acc[mi][ni], a[mi], bl[ni]);
            #pragma unroll
            for (int mi = 0; mi < 4; mi++) ldsm_x4(a[mi], sAl + aOff[mi] + ko);
            #pragma unroll
            for (int mi = 0; mi < 4; mi++)
                #pragma unroll
                for (int ni = 0; ni < 4; ni++) mma_bf16(acc[mi][ni], a[mi], bh[ni]);
        }
        __syncthreads();
    }

    // epilogue
    int lr = lane >> 2, lc = (lane & 3) * 2;
    int r0 = bm + warp_m * 64;
    int c0 = bn + warp_n * 32;
    #pragma unroll
    for (int mi = 0; mi < 4; mi++) {
        int m1 = r0 + mi * 16 + lr;
        int m2 = m1 + 8;
        float bv1 = bias ? bias[m1] : 0.0f;
        float bv2 = bias ? bias[m2] : 0.0f;
        #pragma unroll
        for (int ni = 0; ni < 4; ni++) {
            int n = c0 + ni * 8 + lc;
            float2 v1 = make_float2(acc[mi][ni][0] + bv1, acc[mi][ni][1] + bv1);
            float2 v2 = make_float2(acc[mi][ni][2] + bv2, acc[mi][ni][3] + bv2);
            *(float2*)(C + (size_t)m1 * N + n) = v1;
            *(float2*)(C + (size_t)m2 * N + n) = v2;
        }
    }
}

// ========================= attention tail ==================================
__global__ void score_softmax() {
    int n = blockIdx.x * blockDim.x + threadIdx.x;
    float a0 = 0.f, a1 = 0.f, a2 = 0.f, a3 = 0.f;
    for (int l = 0; l < LCH; l++) {
        float lq = g_Lq[l * NPTS + n];
        a0 += g_keys[(0 * LCH + l) * NPTS + n] * lq;
        a1 += g_keys[(1 * LCH + l) * NPTS + n] * lq;
        a2 += g_keys[(2 * LCH + l) * NPTS + n] * lq;
        a3 += g_keys[(3 * LCH + l) * NPTS + n] * lq;
    }
    const float inv = 0.04419417382415922f;  // 1/sqrt(512)
    a0 *= inv; a1 *= inv; a2 *= inv; a3 *= inv;
    float m = fmaxf(fmaxf(a0, a1), fmaxf(a2, a3));
    float e0 = expf(a0 - m), e1 = expf(a1 - m), e2 = expf(a2 - m), e3 = expf(a3 - m);
    float s = e0 + e1 + e2 + e3;
    g_wmap[0 * NPTS + n] = e0 / s;
    g_wmap[1 * NPTS + n] = e1 / s;
    g_wmap[2 * NPTS + n] = e2 / s;
    g_wmap[3 * NPTS + n] = e3 / s;
}

__global__ void compute_t() {
    size_t i = (size_t)blockIdx.x * blockDim.x + threadIdx.x;
    int n = (int)(i & (NPTS - 1));
    float w0 = g_wmap[0 * NPTS + n];
    float w1 = g_wmap[1 * NPTS + n];
    float w2 = g_wmap[2 * NPTS + n];
    float w3 = g_wmap[3 * NPTS + n];
    const size_t HS = (size_t)LCH * NPTS;
    float z = w0 * g_keys[i] + w1 * g_keys[HS + i]
            + w2 * g_keys[2 * HS + i] + w3 * g_keys[3 * HS + i];
    g_t[i] = z + g_Lq[i];
}

__global__ __launch_bounds__(256)
void layernorm(const float* __restrict__ lnw, const float* __restrict__ lnb) {
    int l = blockIdx.x;
    float* row = g_t + (size_t)l * NPTS;
    float s = 0.f, ss = 0.f;
    for (int n = threadIdx.x; n < NPTS; n += 256) {
        float v = row[n];
        s += v; ss += v * v;
    }
    __shared__ float rs[8], rss[8];
    for (int o = 16; o > 0; o >>= 1) {
        s  += __shfl_down_sync(0xffffffffu, s,  o);
        ss += __shfl_down_sync(0xffffffffu, ss, o);
    }
    int wid = threadIdx.x >> 5, lid = threadIdx.x & 31;
    if (lid == 0) { rs[wid] = s; rss[wid] = ss; }
    __syncthreads();
    if (wid == 0) {
        s  = (lid < 8) ? rs[lid]  : 0.f;
        ss = (lid < 8) ? rss[lid] : 0.f;
        for (int o = 4; o > 0; o >>= 1) {
            s  += __shfl_down_sync(0xffffffffu, s,  o);
            ss += __shfl_down_sync(0xffffffffu, ss, o);
        }
        if (lid == 0) { rs[0] = s; rss[0] = ss; }
    }
    __syncthreads();
    float mu = rs[0] * (1.0f / NPTS);
    float var = rss[0] * (1.0f / NPTS) - mu * mu;
    float rstd = rsqrtf(var + 1e-5f);
    for (int n = threadIdx.x; n < NPTS; n += 256)
        row[n] = (row[n] - mu) * rstd * lnw[n] + lnb[n];
}

__global__ void copy_wmap(float* __restrict__ out) {
    int i = blockIdx.x * blockDim.x + threadIdx.x;
    if (i < HEADS * NPTS) out[i] = g_wmap[i];
}

// ========================= launch ==========================================
extern "C" void kernel_launch(void* const* d_in, const int* in_sizes, int n_in,
                              void* d_out, int out_size) {
    const float* point_features = (const float*)d_in[0];
    const float* keypoints      = (const float*)d_in[1];
    const float* bev_features   = (const float*)d_in[2];
    const float* conv_L_w       = (const float*)d_in[3];
    const float* conv_L_b       = (const float*)d_in[4];
    const float* img_head_w     = (const float*)d_in[5];
    const float* img_head_b     = (const float*)d_in[6];
    const float* ln_w           = (const float*)d_in[7];
    const float* ln_b           = (const float*)d_in[8];
    const float* conv_fusion_w  = (const float*)d_in[9];
    const float* conv_fusion_b  = (const float*)d_in[10];
    float* out = (float*)d_out;

    cudaFuncSetAttribute(gemm_bf16x3, cudaFuncAttributeMaxDynamicSharedMemorySize, GEMM_SMEM);

    float *p_img, *p_Lq, *p_keys, *p_t;
    cudaGetSymbolAddress((void**)&p_img,  g_img);
    cudaGetSymbolAddress((void**)&p_Lq,   g_Lq);
    cudaGetSymbolAddress((void**)&p_keys, g_keys);
    cudaGetSymbolAddress((void**)&p_t,    g_t);
    __nv_bfloat16 *wKh, *wKl, *wLh, *wLl, *wFh, *wFl, *imgTh, *imgTl, *pfTh, *pfTl, *tTh, *tTl;
    cudaGetSymbolAddress((void**)&wKh, g_wK_hi);  cudaGetSymbolAddress((void**)&wKl, g_wK_lo);
    cudaGetSymbolAddress((void**)&wLh, g_wL_hi);  cudaGetSymbolAddress((void**)&wLl, g_wL_lo);
    cudaGetSymbolAddress((void**)&wFh, g_wF_hi);  cudaGetSymbolAddress((void**)&wFl, g_wF_lo);
    cudaGetSymbolAddress((void**)&imgTh, g_imgT_hi); cudaGetSymbolAddress((void**)&imgTl, g_imgT_lo);
    cudaGetSymbolAddress((void**)&pfTh, g_pfT_hi); cudaGetSymbolAddress((void**)&pfTl, g_pfT_lo);
    cudaGetSymbolAddress((void**)&tTh, g_tT_hi);  cudaGetSymbolAddress((void**)&tTl, g_tT_lo);

    // 1) bilinear params + BEV gather
    prep_points<<<(NPTS + 255) / 256, 256>>>(keypoints);
    gather_bev<<<dim3(NPTS / 256, ICH), 256>>>(bev_features);

    // 2) weight splits (K-major already)
    cvt_split<<<(HEADS * LCH * ICH + 255) / 256, 256>>>(img_head_w, wKh, wKl, HEADS * LCH * ICH);
    cvt_split<<<(LCH * LCH + 255) / 256, 256>>>(conv_L_w, wLh, wLl, LCH * LCH);
    cvt_split<<<(LCH * LCH + 255) / 256, 256>>>(conv_fusion_w, wFh, wFl, LCH * LCH);

    // 3) activation transposes+splits
    cvt_split_T<<<dim3(NPTS / 32, LCH / 32), 256>>>(point_features, pfTh, pfTl, LCH, NPTS);
    cvt_split_T<<<dim3(NPTS / 32, ICH / 32), 256>>>(p_img, imgTh, imgTl, ICH, NPTS);

    // 4) L_query = conv_L_w @ pf + b   (512 x 4096, K=512)
    gemm_bf16x3<<<dim3(NPTS / 128, LCH / 128), 256, GEMM_SMEM>>>(
        wLh, wLl, pfTh, pfTl, conv_L_b, p_Lq, LCH, NPTS, LCH);

    // 5) keys = img_head_w @ img + b   (2048 x 4096, K=1024)
    gemm_bf16x3<<<dim3(NPTS / 128, (HEADS * LCH) / 128), 256, GEMM_SMEM>>>(
        wKh, wKl, imgTh, imgTl, img_head_b, p_keys, HEADS * LCH, NPTS, ICH);

    // 6) attention tail
    score_softmax<<<NPTS / 256, 256>>>();
    compute_t<<<(LCH * NPTS) / 256, 256>>>();
    layernorm<<<LCH, 256>>>(ln_w, ln_b);

    // 7) fusion = conv_fusion_w @ t + b  -> out
    cvt_split_T<<<dim3(NPTS / 32, LCH / 32), 256>>>(p_t, tTh, tTl, LCH, NPTS);
    gemm_bf16x3<<<dim3(NPTS / 128, LCH / 128), 256, GEMM_SMEM>>>(
        wFh, wFl, tTh, tTl, conv_fusion_b, out, LCH, NPTS, LCH);

    // 8) weightmap tail
    if (out_size >= LCH * NPTS + HEADS * NPTS) {
        copy_wmap<<<(HEADS * NPTS + 255) / 256, 256>>>(out + (size_t)LCH * NPTS);
    }
}